// round 6
// baseline (speedup 1.0000x reference)
#include <cuda_runtime.h>
#include <cstdint>

typedef unsigned long long U64;

__device__ __forceinline__ U64 pack2(float x) {
    U64 r; asm("mov.b64 %0, {%1, %1};" : "=l"(r) : "f"(x)); return r;
}
__device__ __forceinline__ void fma2(U64 &acc, U64 a, U64 b) {
    asm("fma.rn.f32x2 %0, %1, %2, %0;" : "+l"(acc) : "l"(a), "l"(b));
}
__device__ __forceinline__ float hsum2(U64 a) {
    float lo, hi; asm("mov.b64 {%0,%1}, %2;" : "=f"(lo), "=f"(hi) : "l"(a));
    return lo + hi;
}
__device__ __forceinline__ float sigmoid_f(float x) {
    return 1.f / (1.f + __expf(-x));
}
__device__ __forceinline__ float tanh_exp(float x) {
    float e = __expf(2.f * x);
    return 1.f - __fdividef(2.f, e + 1.f);
}

#define B_    256
#define T_    1024
#define F_    128
#define UU    64
#define NPRE  320   // P cols: [Emu_x(64) | Elv_x(64) | Wg_x(192)]
#define NW1   512

__device__ float g_Wc[F_ * NPRE];
__device__ float g_W1p[UU * NW1];          // k-pair + thread-role permuted (see prep)
__device__ float g_P[B_ * T_ * NPRE];

// ---------------------------------------------------------------------------
// Prep A: g_Wc = W_in (128x128) @ [Emu[:128] | Elv[:128] | Wg[:128]]
// ---------------------------------------------------------------------------
__global__ void k_prep_wc(const float* __restrict__ Win,
                          const float* __restrict__ Emu,
                          const float* __restrict__ Elv,
                          const float* __restrict__ Wg) {
    int r = blockIdx.x;
    int c = threadIdx.x;
    float s = 0.f;
    if (c < 64) {
        for (int k = 0; k < F_; k++) s += Win[r*F_ + k] * Emu[k*64 + c];
    } else if (c < 128) {
        int j = c - 64;
        for (int k = 0; k < F_; k++) s += Win[r*F_ + k] * Elv[k*64 + j];
    } else {
        int j = c - 128;
        for (int k = 0; k < F_; k++) s += Win[r*F_ + k] * Wg[k*192 + j];
    }
    g_Wc[r*NPRE + c] = s;
}

// ---------------------------------------------------------------------------
// Prep B: role-permuted, k-pair-packed W1 (unchanged from round 4/5)
// ---------------------------------------------------------------------------
__global__ void k_prep_w1(const float* __restrict__ S,
                          const float* __restrict__ Pmu,
                          const float* __restrict__ Plv,
                          const float* __restrict__ Emu,
                          const float* __restrict__ Elv,
                          const float* __restrict__ R) {
    int r = blockIdx.x;      // k index 0..63
    int c = threadIdx.x;     // original col 0..511
    float v;
    if (c < 64) {
        v = S[r*64 + c];
    } else {
        int j = c - 64;
        float s = 0.f;
        if (j < 64)       { for (int k = 0; k < 64; k++) s += S[r*64+k] * Pmu[k*64 + j]; }
        else if (j < 128) { int jj = j-64;  for (int k = 0; k < 64; k++) s += S[r*64+k] * Plv[k*64 + jj]; }
        else if (j < 192) { int jj = j-128; for (int k = 0; k < 64; k++) s += S[r*64+k] * Emu[(128+k)*64 + jj]; }
        else if (j < 256) { int jj = j-192; for (int k = 0; k < 64; k++) s += S[r*64+k] * Elv[(128+k)*64 + jj]; }
        else              { int jj = j-256; for (int k = 0; k < 64; k++) s += S[r*64+k] * R[k*192 + jj]; }
        v = s;
    }
    int slot;
    if      (c < 64)  slot = 2*(128 + (c >> 1)) + (c & 1);
    else if (c < 128) slot = 2*(64 + (c - 64));
    else if (c < 192) slot = 2*(64 + (c - 128)) + 1;
    else if (c < 256) slot = 2*(c - 192);
    else if (c < 320) slot = 2*(c - 256) + 1;
    else              slot = 2*(160 + ((c - 320) >> 1)) + ((c - 320) & 1);
    g_W1p[(r >> 1) * 1024 + 2*slot + (r & 1)] = v;
}

// ---------------------------------------------------------------------------
// GEMM v3: K-SIMD f32x2, zero pack2 MOVs, small accumulator footprint.
// Tile BM=64 x BN=64, 256 threads: per-thread 2 rows x 8 cols (16 U64 acc).
// sBp: k-pair packed, per-colgroup chunks padded to 80B -> 8 cgs hit 8
// distinct bank groups (conflict-free LDS.128).
// ---------------------------------------------------------------------------
#define GBM2 64
#define GBN2 64
#define SA2_STRIDE 130                   // floats; 520B/row (8B aligned)
#define SBP_KP_STRIDE 160                // floats per kp row: 8 cg * 20
#define GEMM_SMEM_BYTES ((GBM2*SA2_STRIDE + 64*SBP_KP_STRIDE) * 4)

__global__ void __launch_bounds__(256, 2) k_gemm_p(const float* __restrict__ x) {
    extern __shared__ float sm[];
    float* sA  = sm;                          // [64][130], k contiguous
    float* sBp = sm + GBM2 * SA2_STRIDE;      // [64 kp][8 cg][20]
    int tid = threadIdx.x;
    int nb = blockIdx.x * GBN2;
    int mb = blockIdx.y * GBM2;

    // fill A: 64 rows x 128 floats (k-contiguous), float4 gmem loads
    for (int i = tid; i < 64 * 32; i += 256) {
        int r = i >> 5, c4 = (i & 31) << 2;
        float4 v = *(const float4*)(x + (mb + r) * F_ + c4);
        float* d = sA + r * SA2_STRIDE + c4;
        *(float2*)d = make_float2(v.x, v.y);
        *(float2*)(d + 2) = make_float2(v.z, v.w);
    }
    // fill B: k-pair packed with per-cg 20-float chunks
    for (int i = tid; i < 128 * 16; i += 256) {
        int k = i >> 4, c4 = (i & 15) << 2;          // c4 = 0,4,..,60
        float4 v = *(const float4*)(g_Wc + k * NPRE + nb + c4);
        int kp = k >> 1, par = k & 1;
        float* base = sBp + kp * SBP_KP_STRIDE;
        // col c -> offset (c>>3)*20 + ((c&7)<<1) + par
        int c0i = c4;
        base[((c0i+0) >> 3)*20 + (((c0i+0)&7)<<1) + par] = v.x;
        base[((c0i+1) >> 3)*20 + (((c0i+1)&7)<<1) + par] = v.y;
        base[((c0i+2) >> 3)*20 + (((c0i+2)&7)<<1) + par] = v.z;
        base[((c0i+3) >> 3)*20 + (((c0i+3)&7)<<1) + par] = v.w;
    }
    __syncthreads();

    int cg = tid & 7;        // 8 col-groups of 8 cols
    int rg = tid >> 3;       // 32 row-groups of 2 rows
    int r0 = rg << 1;

    U64 acc[2][8];
#pragma unroll
    for (int i = 0; i < 2; i++)
#pragma unroll
        for (int j = 0; j < 8; j++) acc[i][j] = 0ull;

    const float* a0p = sA + (r0+0) * SA2_STRIDE;
    const float* a1p = sA + (r0+1) * SA2_STRIDE;
    const float* bpp = sBp + cg * 20;

#pragma unroll 8
    for (int kp = 0; kp < 64; kp++) {
        U64 a0 = *(const U64*)(a0p + 2*kp);
        U64 a1 = *(const U64*)(a1p + 2*kp);
        const float* bp = bpp + kp * SBP_KP_STRIDE;
        ulonglong2 q01 = *(const ulonglong2*)(bp);
        ulonglong2 q23 = *(const ulonglong2*)(bp + 4);
        ulonglong2 q45 = *(const ulonglong2*)(bp + 8);
        ulonglong2 q67 = *(const ulonglong2*)(bp + 12);
        fma2(acc[0][0], a0, q01.x); fma2(acc[0][1], a0, q01.y);
        fma2(acc[0][2], a0, q23.x); fma2(acc[0][3], a0, q23.y);
        fma2(acc[0][4], a0, q45.x); fma2(acc[0][5], a0, q45.y);
        fma2(acc[0][6], a0, q67.x); fma2(acc[0][7], a0, q67.y);
        fma2(acc[1][0], a1, q01.x); fma2(acc[1][1], a1, q01.y);
        fma2(acc[1][2], a1, q23.x); fma2(acc[1][3], a1, q23.y);
        fma2(acc[1][4], a1, q45.x); fma2(acc[1][5], a1, q45.y);
        fma2(acc[1][6], a1, q67.x); fma2(acc[1][7], a1, q67.y);
    }

#pragma unroll
    for (int i = 0; i < 2; i++) {
        float4 v0, v1;
        v0.x = hsum2(acc[i][0]); v0.y = hsum2(acc[i][1]);
        v0.z = hsum2(acc[i][2]); v0.w = hsum2(acc[i][3]);
        v1.x = hsum2(acc[i][4]); v1.y = hsum2(acc[i][5]);
        v1.z = hsum2(acc[i][6]); v1.w = hsum2(acc[i][7]);
        float* dst = g_P + (long)(mb + r0 + i) * NPRE + nb + (cg << 3);
        *(float4*)dst = v0;
        *(float4*)(dst + 4) = v1;
    }
}

// ---------------------------------------------------------------------------
// Recurrent kernel v4 (byte-identical to round 4/5 — measured 1155 us)
// ---------------------------------------------------------------------------
#define OFF_W2  0
#define OFF_B0  12288
#define OFF_B1  12480
#define OFF_HP  12672
#define OFF_MH  12800
#define OFF_G   13184
#define OFF_H   13952
#define OFF_Z2  14080
#define RNN_SMEM_FLOATS 14336
#define RNN_SMEM_BYTES  (RNN_SMEM_FLOATS * 4)

__global__ void __launch_bounds__(256, 1) k_rnn(const float* __restrict__ gbias,
                                                const float* __restrict__ gruk,
                                                float* __restrict__ out) {
    extern __shared__ float sm[];
    float* sW2 = sm + OFF_W2;
    float* sB0 = sm + OFF_B0;
    float* sB1 = sm + OFF_B1;
    float* sHP = sm + OFF_HP;
    float* sMH = sm + OFF_MH;
    float* sG  = sm + OFF_G;
    float* sH  = sm + OFF_H;
    U64*   sZ2 = (U64*)(sm + OFF_Z2);

    int tid = threadIdx.x;
    int b0  = blockIdx.x * 2;

    for (int i = tid; i < (64*192)/4; i += 256)
        *(float4*)(sW2 + i*4) = *(const float4*)(gruk + 128*192 + i*4);
    if (tid < 96)
        *(float4*)(sB0 + tid*4) = *(const float4*)(gbias + tid*4);
    if (tid < 128) sH[tid] = 0.f;

    U64 w1a[32], w1b[32];
#pragma unroll
    for (int i = 0; i < 32; i++) {
        ulonglong2 v = *(const ulonglong2*)(g_W1p + i * 1024 + (tid << 2));
        w1a[i] = v.x; w1b[i] = v.y;
    }

    int re = tid >> 6, ue = tid & 63;
    int hf = (tid < 96) ? 0 : 1;
    int j2 = (tid < 96) ? tid : (tid - 96);
    int kb = hf << 5;

    const int SEQ = B_ * T_ * UU;
    const float* PZ0 = g_P + (long)(b0)     * T_ * NPRE + tid;
    const float* PZ1 = g_P + (long)(b0 + 1) * T_ * NPRE + tid;
    const float* PG  = g_P + (long)(b0 + re)* T_ * NPRE + 128 + ue;

    float cz0=0,cz1=0,cz2=0,cz3=0, cg0=0,cg1=0,cg2=0;
    if (tid < 64) {
        cz0 = PZ0[0];  cz1 = PZ0[64];
        cz2 = PZ1[0];  cz3 = PZ1[64];
    }
    if (tid < 128) {
        cg0 = PG[0];   cg1 = PG[64];  cg2 = PG[128];
    }
    __syncthreads();

#pragma unroll 1
    for (int t = 0; t < T_; t++) {
        int tn = (t + 1 < T_) ? (t + 1) : t;
        long offn = (long)tn * NPRE;
        float nz0=0,nz1=0,nz2=0,nz3=0, ng0=0,ng1=0,ng2=0;
        if (tid < 64) {
            nz0 = PZ0[offn];      nz1 = PZ0[offn + 64];
            nz2 = PZ1[offn];      nz3 = PZ1[offn + 64];
        }
        if (tid < 128) {
            ng0 = PG[offn];  ng1 = PG[offn + 64];  ng2 = PG[offn + 128];
        }

        const ulonglong2* h0 = (const ulonglong2*)(sH);
        const ulonglong2* h1 = (const ulonglong2*)(sH + 64);
        U64 a00 = 0ull, a01 = 0ull, a10 = 0ull, a11 = 0ull;
#pragma unroll
        for (int i = 0; i < 16; i++) {
            ulonglong2 ha = h0[i];
            ulonglong2 hb = h1[i];
            fma2(a00, ha.x, w1a[2*i]);   fma2(a01, ha.x, w1b[2*i]);
            fma2(a10, hb.x, w1a[2*i]);   fma2(a11, hb.x, w1b[2*i]);
            fma2(a00, ha.y, w1a[2*i+1]); fma2(a01, ha.y, w1b[2*i+1]);
            fma2(a10, hb.y, w1a[2*i+1]); fma2(a11, hb.y, w1b[2*i+1]);
        }
        float y00 = hsum2(a00), y01 = hsum2(a01);
        float y10 = hsum2(a10), y11 = hsum2(a11);

        if (tid < 64) {
            float qmu0 = y00 + cz0, qlv0 = y01 + cz1;
            float qmu1 = y10 + cz2, qlv1 = y11 + cz3;
            float z0 = 0.5f * __expf(qlv0) + qmu0;
            float z1 = 0.5f * __expf(qlv1) + qmu1;
            sZ2[tid]      = pack2(z0);
            sZ2[64 + tid] = pack2(z1);
            int base0 = (b0 * T_ + t) * UU + tid;
            int base1 = base0 + T_ * UU;
            out[base0]          = z0;
            out[base0 + SEQ]    = qmu0;
            out[base0 + 3*SEQ]  = qlv0;
            out[base1]          = z1;
            out[base1 + SEQ]    = qmu1;
            out[base1 + 3*SEQ]  = qlv1;
        } else if (tid < 128) {
            int u = tid - 64;
            int base0 = (b0 * T_ + t) * UU + u;
            int base1 = base0 + T_ * UU;
            out[base0 + 2*SEQ] = y00;
            out[base0 + 4*SEQ] = y01;
            out[base1 + 2*SEQ] = y10;
            out[base1 + 4*SEQ] = y11;
        } else if (tid < 160) {
            int j = tid - 128;
            *(float2*)(sHP + 2*j)       = make_float2(y00, y01);
            *(float2*)(sHP + 64 + 2*j)  = make_float2(y10, y11);
        } else {
            int j = tid - 160;
            *(float2*)(sMH + 2*j)        = make_float2(y00, y01);
            *(float2*)(sMH + 192 + 2*j)  = make_float2(y10, y11);
        }
        __syncthreads();

        if (tid < 192) {
            U64 g0 = 0ull, g1 = 0ull;
            const float* w2 = sW2 + (j2 << 1);
#pragma unroll
            for (int kk = 0; kk < 32; kk += 2) {
                int k = kb + kk;
                ulonglong2 z0 = *(const ulonglong2*)(sZ2 + k);
                ulonglong2 z1 = *(const ulonglong2*)(sZ2 + 64 + k);
                U64 wa = *(const U64*)(w2 + k * 192);
                U64 wb = *(const U64*)(w2 + (k+1) * 192);
                fma2(g0, z0.x, wa); fma2(g1, z1.x, wa);
                fma2(g0, z0.y, wb); fma2(g1, z1.y, wb);
            }
            *(U64*)(sG + ((hf << 1) + 0) * 192 + (j2 << 1)) = g0;
            *(U64*)(sG + ((hf << 1) + 1) * 192 + (j2 << 1)) = g1;
        }
        __syncthreads();

        if (tid < 128) {
            const float* Ga = sG + re * 192;
            const float* Gb = sG + (2 + re) * 192;
            float hp  = sHP[re * 64 + ue];
            float mhz = sMH[re * 192 + ue]        + sB1[ue];
            float mhr = sMH[re * 192 + 64 + ue]   + sB1[64 + ue];
            float mhh = sMH[re * 192 + 128 + ue]  + sB1[128 + ue];
            float mxz = cg0 + Ga[ue]        + Gb[ue]        + sB0[ue];
            float mxr = cg1 + Ga[64 + ue]   + Gb[64 + ue]   + sB0[64 + ue];
            float mxh = cg2 + Ga[128 + ue]  + Gb[128 + ue]  + sB0[128 + ue];
            float zt = sigmoid_f(mxz + mhz);
            float rt = sigmoid_f(mxr + mhr);
            float hh = tanh_exp(mxh + rt * mhh);
            sH[re * 64 + ue] = zt * hp + (1.f - zt) * hh;
        }
        __syncthreads();

        cz0 = nz0; cz1 = nz1; cz2 = nz2; cz3 = nz3;
        cg0 = ng0; cg1 = ng1; cg2 = ng2;
    }
}

// ---------------------------------------------------------------------------
extern "C" void kernel_launch(void* const* d_in, const int* in_sizes, int n_in,
                              void* d_out, int out_size) {
    const float* x   = (const float*)d_in[0];
    const float* Win = (const float*)d_in[1];
    const float* S   = (const float*)d_in[2];
    const float* Emu = (const float*)d_in[3];
    const float* Elv = (const float*)d_in[4];
    const float* Pmu = (const float*)d_in[5];
    const float* Plv = (const float*)d_in[6];
    const float* Wg  = (const float*)d_in[7];
    const float* R   = (const float*)d_in[8];
    const float* gb  = (const float*)d_in[9];

    cudaFuncSetAttribute(k_gemm_p, cudaFuncAttributeMaxDynamicSharedMemorySize, GEMM_SMEM_BYTES);
    cudaFuncSetAttribute(k_rnn,    cudaFuncAttributeMaxDynamicSharedMemorySize, RNN_SMEM_BYTES);

    k_prep_wc<<<128, 320>>>(Win, Emu, Elv, Wg);
    k_prep_w1<<<64, 512>>>(S, Pmu, Plv, Emu, Elv, R);

    dim3 gg(5, 4096);   // N-tiles fastest: same-A blocks adjacent -> L2 reuse
    k_gemm_p<<<gg, 256, GEMM_SMEM_BYTES>>>(x);

    k_rnn<<<128, 256, RNN_SMEM_BYTES>>>(gb, Wg, (float*)d_out);
}

// round 7
// speedup vs baseline: 1.0269x; 1.0269x over previous
#include <cuda_runtime.h>
#include <cstdint>

typedef unsigned long long U64;

__device__ __forceinline__ U64 pack2(float x) {
    U64 r; asm("mov.b64 %0, {%1, %1};" : "=l"(r) : "f"(x)); return r;
}
__device__ __forceinline__ void fma2(U64 &acc, U64 a, U64 b) {
    asm("fma.rn.f32x2 %0, %1, %2, %0;" : "+l"(acc) : "l"(a), "l"(b));
}
__device__ __forceinline__ float hsum2(U64 a) {
    float lo, hi; asm("mov.b64 {%0,%1}, %2;" : "=f"(lo), "=f"(hi) : "l"(a));
    return lo + hi;
}
__device__ __forceinline__ float sigmoid_f(float x) {
    return 1.f / (1.f + __expf(-x));
}
__device__ __forceinline__ float tanh_exp(float x) {
    float e = __expf(2.f * x);
    return 1.f - __fdividef(2.f, e + 1.f);
}

#define B_    256
#define T_    1024
#define F_    128
#define UU    64
#define NPRE  320   // P cols: [Emu_x(64) | Elv_x(64) | Wg_x(192)]
#define NW1   512

__device__ float g_Wc[F_ * NPRE];
__device__ float g_W1p[UU * NW1];          // k-pair + thread-role permuted
__device__ float g_P[B_ * T_ * NPRE];

// ---------------------------------------------------------------------------
// Prep A: g_Wc = W_in (128x128) @ [Emu[:128] | Elv[:128] | Wg[:128]]
// ---------------------------------------------------------------------------
__global__ void k_prep_wc(const float* __restrict__ Win,
                          const float* __restrict__ Emu,
                          const float* __restrict__ Elv,
                          const float* __restrict__ Wg) {
    int r = blockIdx.x;
    int c = threadIdx.x;
    float s = 0.f;
    if (c < 64) {
        for (int k = 0; k < F_; k++) s += Win[r*F_ + k] * Emu[k*64 + c];
    } else if (c < 128) {
        int j = c - 64;
        for (int k = 0; k < F_; k++) s += Win[r*F_ + k] * Elv[k*64 + j];
    } else {
        int j = c - 128;
        for (int k = 0; k < F_; k++) s += Win[r*F_ + k] * Wg[k*192 + j];
    }
    g_Wc[r*NPRE + c] = s;
}

// ---------------------------------------------------------------------------
// Prep B: role-permuted, k-pair-packed W1 (unchanged)
// ---------------------------------------------------------------------------
__global__ void k_prep_w1(const float* __restrict__ S,
                          const float* __restrict__ Pmu,
                          const float* __restrict__ Plv,
                          const float* __restrict__ Emu,
                          const float* __restrict__ Elv,
                          const float* __restrict__ R) {
    int r = blockIdx.x;      // k index 0..63
    int c = threadIdx.x;     // original col 0..511
    float v;
    if (c < 64) {
        v = S[r*64 + c];
    } else {
        int j = c - 64;
        float s = 0.f;
        if (j < 64)       { for (int k = 0; k < 64; k++) s += S[r*64+k] * Pmu[k*64 + j]; }
        else if (j < 128) { int jj = j-64;  for (int k = 0; k < 64; k++) s += S[r*64+k] * Plv[k*64 + jj]; }
        else if (j < 192) { int jj = j-128; for (int k = 0; k < 64; k++) s += S[r*64+k] * Emu[(128+k)*64 + jj]; }
        else if (j < 256) { int jj = j-192; for (int k = 0; k < 64; k++) s += S[r*64+k] * Elv[(128+k)*64 + jj]; }
        else              { int jj = j-256; for (int k = 0; k < 64; k++) s += S[r*64+k] * R[k*192 + jj]; }
        v = s;
    }
    int slot;
    if      (c < 64)  slot = 2*(128 + (c >> 1)) + (c & 1);
    else if (c < 128) slot = 2*(64 + (c - 64));
    else if (c < 192) slot = 2*(64 + (c - 128)) + 1;
    else if (c < 256) slot = 2*(c - 192);
    else if (c < 320) slot = 2*(c - 256) + 1;
    else              slot = 2*(160 + ((c - 320) >> 1)) + ((c - 320) & 1);
    g_W1p[(r >> 1) * 1024 + 2*slot + (r & 1)] = v;
}

// ---------------------------------------------------------------------------
// GEMM (round-5 version, verbatim — measured best ~700us)
// ---------------------------------------------------------------------------
#define GBM 128
#define GBN 64
#define SA_STRIDE 132
#define GEMM_SMEM_BYTES ((128*SA_STRIDE + 128*GBN) * 4)

__global__ void __launch_bounds__(256, 2) k_gemm_p(const float* __restrict__ x) {
    extern __shared__ float sm[];
    float* sA = sm;
    float* sB = sm + 128 * SA_STRIDE;
    int tid = threadIdx.x;
    int mb = blockIdx.y * GBM;
    int nb = blockIdx.x * GBN;

    for (int i = tid; i < 128 * 32; i += 256) {
        int r = i >> 5, c4 = (i & 31) << 2;
        float4 v = *(const float4*)(x + (mb + r) * F_ + c4);
        *(float4*)(sA + r * SA_STRIDE + c4) = v;
    }
    for (int i = tid; i < 128 * 16; i += 256) {
        int k = i >> 4, c4 = (i & 15) << 2;
        *(float4*)(sB + k * GBN + c4) = *(const float4*)(g_Wc + k * NPRE + nb + c4);
    }
    __syncthreads();

    int cg = tid & 7, rg = tid >> 3;
    int c0 = cg << 3, r0 = rg << 2;

    U64 acc[4][4];
#pragma unroll
    for (int i = 0; i < 4; i++)
#pragma unroll
        for (int j = 0; j < 4; j++) acc[i][j] = 0ull;

#pragma unroll 4
    for (int k = 0; k < 128; k++) {
        float a0 = sA[(r0+0)*SA_STRIDE + k];
        float a1 = sA[(r0+1)*SA_STRIDE + k];
        float a2 = sA[(r0+2)*SA_STRIDE + k];
        float a3 = sA[(r0+3)*SA_STRIDE + k];
        ulonglong2 b01 = *(const ulonglong2*)(sB + k*GBN + c0);
        ulonglong2 b23 = *(const ulonglong2*)(sB + k*GBN + c0 + 4);
        U64 p0 = pack2(a0), p1 = pack2(a1), p2 = pack2(a2), p3 = pack2(a3);
        fma2(acc[0][0], p0, b01.x); fma2(acc[0][1], p0, b01.y);
        fma2(acc[0][2], p0, b23.x); fma2(acc[0][3], p0, b23.y);
        fma2(acc[1][0], p1, b01.x); fma2(acc[1][1], p1, b01.y);
        fma2(acc[1][2], p1, b23.x); fma2(acc[1][3], p1, b23.y);
        fma2(acc[2][0], p2, b01.x); fma2(acc[2][1], p2, b01.y);
        fma2(acc[2][2], p2, b23.x); fma2(acc[2][3], p2, b23.y);
        fma2(acc[3][0], p3, b01.x); fma2(acc[3][1], p3, b01.y);
        fma2(acc[3][2], p3, b23.x); fma2(acc[3][3], p3, b23.y);
    }

#pragma unroll
    for (int i = 0; i < 4; i++) {
        float* dst = g_P + (mb + r0 + i) * NPRE + nb + c0;
        ulonglong2 v0; v0.x = acc[i][0]; v0.y = acc[i][1];
        *(ulonglong2*)dst = v0;
        ulonglong2 v1; v1.x = acc[i][2]; v1.y = acc[i][3];
        *(ulonglong2*)(dst + 4) = v1;
    }
}

// ---------------------------------------------------------------------------
// Recurrent kernel v5: 2 phases/step. Phase 1 = M1 (+role epilogue).
// Phase 2 = fused M2+gates on tid<64 only (full-K col-triple per thread,
// both rows: W2 read once, no sG, one barrier removed).
// ---------------------------------------------------------------------------
#define OFF_W2P 0              // [32 kp][384] : [kp][2c+par] = W2[2kp+par][c]
#define OFF_B0  12288          // [192]
#define OFF_B1  12480          // [192]
#define OFF_HP  12672          // [2][64]
#define OFF_MH  12800          // [2][192]
#define OFF_H   13184          // [2][64]
#define OFF_ZF  13312          // [2][64] plain z
#define RNN_SMEM_FLOATS 13440
#define RNN_SMEM_BYTES  (RNN_SMEM_FLOATS * 4)

__global__ void __launch_bounds__(256, 1) k_rnn(const float* __restrict__ gbias,
                                                const float* __restrict__ gruk,
                                                float* __restrict__ out) {
    extern __shared__ float sm[];
    float* sW2p = sm + OFF_W2P;
    float* sB0  = sm + OFF_B0;
    float* sB1  = sm + OFF_B1;
    float* sHP  = sm + OFF_HP;
    float* sMH  = sm + OFF_MH;
    float* sH   = sm + OFF_H;
    float* sZf  = sm + OFF_ZF;

    int tid = threadIdx.x;
    int b0  = blockIdx.x * 2;

    // --- W2 (gru_recurrent rows of gru_kernel[128:192]) k-pair packed ---
    for (int i = tid; i < 64 * 192; i += 256) {
        int k = i / 192, c = i - k * 192;
        sW2p[(k >> 1) * 384 + 2*c + (k & 1)] = gruk[(128 + k) * 192 + c];
    }
    if (tid < 96)
        *(float4*)(sB0 + tid*4) = *(const float4*)(gbias + tid*4);
    if (tid < 128) sH[tid] = 0.f;

    // --- W1 regs: thread t's two permuted columns, k-pair packed ---
    U64 w1a[32], w1b[32];
#pragma unroll
    for (int i = 0; i < 32; i++) {
        ulonglong2 v = *(const ulonglong2*)(g_W1p + i * 1024 + (tid << 2));
        w1a[i] = v.x; w1b[i] = v.y;
    }

    const int SEQ = B_ * T_ * UU;
    // P pointers: tid<64 loads z-part (4) + gate-part for both rows (6)
    const float* PZ0 = g_P + (long)(b0)     * T_ * NPRE + tid;          // cols u, 64+u
    const float* PZ1 = g_P + (long)(b0 + 1) * T_ * NPRE + tid;
    const float* PG0 = g_P + (long)(b0)     * T_ * NPRE + 128 + tid;    // cols 128/192/256 +u
    const float* PG1 = g_P + (long)(b0 + 1) * T_ * NPRE + 128 + tid;

    float cz0=0,cz1=0,cz2=0,cz3=0;
    float ca0=0,ca1=0,ca2=0, cb0=0,cb1=0,cb2=0;
    if (tid < 64) {
        cz0 = PZ0[0];  cz1 = PZ0[64];
        cz2 = PZ1[0];  cz3 = PZ1[64];
        ca0 = PG0[0];  ca1 = PG0[64];  ca2 = PG0[128];
        cb0 = PG1[0];  cb1 = PG1[64];  cb2 = PG1[128];
    }
    __syncthreads();

#pragma unroll 1
    for (int t = 0; t < T_; t++) {
        // prefetch next step's P (clamped last iter)
        int tn = (t + 1 < T_) ? (t + 1) : t;
        long offn = (long)tn * NPRE;
        float nz0=0,nz1=0,nz2=0,nz3=0, na0=0,na1=0,na2=0, nb0=0,nb1=0,nb2=0;
        if (tid < 64) {
            nz0 = PZ0[offn];       nz1 = PZ0[offn + 64];
            nz2 = PZ1[offn];       nz3 = PZ1[offn + 64];
            na0 = PG0[offn];  na1 = PG0[offn + 64];  na2 = PG0[offn + 128];
            nb0 = PG1[offn];  nb1 = PG1[offn + 64];  nb2 = PG1[offn + 128];
        }

        // ---- M1: both rows, this thread's 2 cols, K-SIMD
        const ulonglong2* h0 = (const ulonglong2*)(sH);
        const ulonglong2* h1 = (const ulonglong2*)(sH + 64);
        U64 a00 = 0ull, a01 = 0ull, a10 = 0ull, a11 = 0ull;
#pragma unroll
        for (int i = 0; i < 16; i++) {
            ulonglong2 ha = h0[i];
            ulonglong2 hb = h1[i];
            fma2(a00, ha.x, w1a[2*i]);   fma2(a01, ha.x, w1b[2*i]);
            fma2(a10, hb.x, w1a[2*i]);   fma2(a11, hb.x, w1b[2*i]);
            fma2(a00, ha.y, w1a[2*i+1]); fma2(a01, ha.y, w1b[2*i+1]);
            fma2(a10, hb.y, w1a[2*i+1]); fma2(a11, hb.y, w1b[2*i+1]);
        }
        float y00 = hsum2(a00), y01 = hsum2(a01);
        float y10 = hsum2(a10), y11 = hsum2(a11);

        // ---- role epilogue
        if (tid < 64) {
            float qmu0 = y00 + cz0, qlv0 = y01 + cz1;
            float qmu1 = y10 + cz2, qlv1 = y11 + cz3;
            float z0 = 0.5f * __expf(qlv0) + qmu0;
            float z1 = 0.5f * __expf(qlv1) + qmu1;
            sZf[tid]      = z0;
            sZf[64 + tid] = z1;
            int base0 = (b0 * T_ + t) * UU + tid;
            int base1 = base0 + T_ * UU;
            out[base0]          = z0;
            out[base0 + SEQ]    = qmu0;
            out[base0 + 3*SEQ]  = qlv0;
            out[base1]          = z1;
            out[base1 + SEQ]    = qmu1;
            out[base1 + 3*SEQ]  = qlv1;
        } else if (tid < 128) {
            int u = tid - 64;
            int base0 = (b0 * T_ + t) * UU + u;
            int base1 = base0 + T_ * UU;
            out[base0 + 2*SEQ] = y00;
            out[base0 + 4*SEQ] = y01;
            out[base1 + 2*SEQ] = y10;
            out[base1 + 4*SEQ] = y11;
        } else if (tid < 160) {
            int j = tid - 128;
            *(float2*)(sHP + 2*j)       = make_float2(y00, y01);
            *(float2*)(sHP + 64 + 2*j)  = make_float2(y10, y11);
        } else {
            int j = tid - 160;
            *(float2*)(sMH + 2*j)        = make_float2(y00, y01);
            *(float2*)(sMH + 192 + 2*j)  = make_float2(y10, y11);
        }
        __syncthreads();

        // ---- fused M2 + gates (tid < 64): full K, both rows, col-triple u
        if (tid < 64) {
            int u = tid;
            U64 az0=0ull, ar0=0ull, ah0=0ull, az1=0ull, ar1=0ull, ah1=0ull;
            const float* wp = sW2p + (u << 1);
#pragma unroll
            for (int kp = 0; kp < 32; kp++) {
                U64 zp0 = *(const U64*)(sZf + 2*kp);        // {z0[2kp], z0[2kp+1]}
                U64 zp1 = *(const U64*)(sZf + 64 + 2*kp);
                const float* w = wp + kp * 384;
                U64 wz = *(const U64*)(w);
                U64 wr = *(const U64*)(w + 128);
                U64 wh = *(const U64*)(w + 256);
                fma2(az0, zp0, wz); fma2(ar0, zp0, wr); fma2(ah0, zp0, wh);
                fma2(az1, zp1, wz); fma2(ar1, zp1, wr); fma2(ah1, zp1, wh);
            }
            float Gz0 = hsum2(az0), Gr0 = hsum2(ar0), Gh0 = hsum2(ah0);
            float Gz1 = hsum2(az1), Gr1 = hsum2(ar1), Gh1 = hsum2(ah1);

            float bz0 = sB0[u], bz1 = sB0[64+u], bz2 = sB0[128+u];
            float rz0 = sB1[u], rz1 = sB1[64+u], rz2 = sB1[128+u];

            // row 0
            {
                float hp  = sHP[u];
                float mhz = sMH[u]        + rz0;
                float mhr = sMH[64 + u]   + rz1;
                float mhh = sMH[128 + u]  + rz2;
                float mxz = ca0 + Gz0 + bz0;
                float mxr = ca1 + Gr0 + bz1;
                float mxh = ca2 + Gh0 + bz2;
                float zt = sigmoid_f(mxz + mhz);
                float rt = sigmoid_f(mxr + mhr);
                float hh = tanh_exp(mxh + rt * mhh);
                sH[u] = zt * hp + (1.f - zt) * hh;
            }
            // row 1
            {
                float hp  = sHP[64 + u];
                float mhz = sMH[192 + u]        + rz0;
                float mhr = sMH[192 + 64 + u]   + rz1;
                float mhh = sMH[192 + 128 + u]  + rz2;
                float mxz = cb0 + Gz1 + bz0;
                float mxr = cb1 + Gr1 + bz1;
                float mxh = cb2 + Gh1 + bz2;
                float zt = sigmoid_f(mxz + mhz);
                float rt = sigmoid_f(mxr + mhr);
                float hh = tanh_exp(mxh + rt * mhh);
                sH[64 + u] = zt * hp + (1.f - zt) * hh;
            }
        }
        __syncthreads();

        cz0 = nz0; cz1 = nz1; cz2 = nz2; cz3 = nz3;
        ca0 = na0; ca1 = na1; ca2 = na2;
        cb0 = nb0; cb1 = nb1; cb2 = nb2;
    }
}

// ---------------------------------------------------------------------------
extern "C" void kernel_launch(void* const* d_in, const int* in_sizes, int n_in,
                              void* d_out, int out_size) {
    const float* x   = (const float*)d_in[0];
    const float* Win = (const float*)d_in[1];
    const float* S   = (const float*)d_in[2];
    const float* Emu = (const float*)d_in[3];
    const float* Elv = (const float*)d_in[4];
    const float* Pmu = (const float*)d_in[5];
    const float* Plv = (const float*)d_in[6];
    const float* Wg  = (const float*)d_in[7];
    const float* R   = (const float*)d_in[8];
    const float* gb  = (const float*)d_in[9];

    cudaFuncSetAttribute(k_gemm_p, cudaFuncAttributeMaxDynamicSharedMemorySize, GEMM_SMEM_BYTES);
    cudaFuncSetAttribute(k_rnn,    cudaFuncAttributeMaxDynamicSharedMemorySize, RNN_SMEM_BYTES);

    k_prep_wc<<<128, 320>>>(Win, Emu, Elv, Wg);
    k_prep_w1<<<64, 512>>>(S, Pmu, Plv, Emu, Elv, R);

    dim3 gg(5, 2048);   // N-tiles fastest: same-A blocks adjacent -> L2 reuse
    k_gemm_p<<<gg, 256, GEMM_SMEM_BYTES>>>(x);

    k_rnn<<<128, 256, RNN_SMEM_BYTES>>>(gb, Wg, (float*)d_out);
}

// round 8
// speedup vs baseline: 1.1369x; 1.1070x over previous
#include <cuda_runtime.h>
#include <cstdint>

typedef unsigned long long U64;

__device__ __forceinline__ U64 pack2(float x) {
    U64 r; asm("mov.b64 %0, {%1, %1};" : "=l"(r) : "f"(x)); return r;
}
__device__ __forceinline__ void fma2(U64 &acc, U64 a, U64 b) {
    asm("fma.rn.f32x2 %0, %1, %2, %0;" : "+l"(acc) : "l"(a), "l"(b));
}
__device__ __forceinline__ float hsum2(U64 a) {
    float lo, hi; asm("mov.b64 {%0,%1}, %2;" : "=f"(lo), "=f"(hi) : "l"(a));
    return lo + hi;
}
__device__ __forceinline__ float sigmoid_f(float x) {
    return 1.f / (1.f + __expf(-x));
}
__device__ __forceinline__ float tanh_exp(float x) {
    float e = __expf(2.f * x);
    return 1.f - __fdividef(2.f, e + 1.f);
}

#define B_    256
#define T_    1024
#define F_    128
#define UU    64
#define NPRE  320   // P cols: [Emu_x(64) | Elv_x(64) | Wg_x(192)]
#define NW1   512

__device__ float g_Wc[F_ * NPRE];
__device__ float g_W1p[UU * NW1];          // k-pair + thread-role permuted
__device__ float g_P[B_ * T_ * NPRE];

// ---------------------------------------------------------------------------
// Prep A: g_Wc = W_in (128x128) @ [Emu[:128] | Elv[:128] | Wg[:128]]
// ---------------------------------------------------------------------------
__global__ void k_prep_wc(const float* __restrict__ Win,
                          const float* __restrict__ Emu,
                          const float* __restrict__ Elv,
                          const float* __restrict__ Wg) {
    int r = blockIdx.x;
    int c = threadIdx.x;
    float s = 0.f;
    if (c < 64) {
        for (int k = 0; k < F_; k++) s += Win[r*F_ + k] * Emu[k*64 + c];
    } else if (c < 128) {
        int j = c - 64;
        for (int k = 0; k < F_; k++) s += Win[r*F_ + k] * Elv[k*64 + j];
    } else {
        int j = c - 128;
        for (int k = 0; k < F_; k++) s += Win[r*F_ + k] * Wg[k*192 + j];
    }
    g_Wc[r*NPRE + c] = s;
}

// ---------------------------------------------------------------------------
// Prep B: role-permuted, k-pair-packed W1 (unchanged)
// ---------------------------------------------------------------------------
__global__ void k_prep_w1(const float* __restrict__ S,
                          const float* __restrict__ Pmu,
                          const float* __restrict__ Plv,
                          const float* __restrict__ Emu,
                          const float* __restrict__ Elv,
                          const float* __restrict__ R) {
    int r = blockIdx.x;      // k index 0..63
    int c = threadIdx.x;     // original col 0..511
    float v;
    if (c < 64) {
        v = S[r*64 + c];
    } else {
        int j = c - 64;
        float s = 0.f;
        if (j < 64)       { for (int k = 0; k < 64; k++) s += S[r*64+k] * Pmu[k*64 + j]; }
        else if (j < 128) { int jj = j-64;  for (int k = 0; k < 64; k++) s += S[r*64+k] * Plv[k*64 + jj]; }
        else if (j < 192) { int jj = j-128; for (int k = 0; k < 64; k++) s += S[r*64+k] * Emu[(128+k)*64 + jj]; }
        else if (j < 256) { int jj = j-192; for (int k = 0; k < 64; k++) s += S[r*64+k] * Elv[(128+k)*64 + jj]; }
        else              { int jj = j-256; for (int k = 0; k < 64; k++) s += S[r*64+k] * R[k*192 + jj]; }
        v = s;
    }
    int slot;
    if      (c < 64)  slot = 2*(128 + (c >> 1)) + (c & 1);
    else if (c < 128) slot = 2*(64 + (c - 64));
    else if (c < 192) slot = 2*(64 + (c - 128)) + 1;
    else if (c < 256) slot = 2*(c - 192);
    else if (c < 320) slot = 2*(c - 256) + 1;
    else              slot = 2*(160 + ((c - 320) >> 1)) + ((c - 320) & 1);
    g_W1p[(r >> 1) * 1024 + 2*slot + (r & 1)] = v;
}

// ---------------------------------------------------------------------------
// GEMM v4: 128 threads/block, per-thread 8 rows x 8 cols. SA_STRIDE=133 (odd)
// -> 8-row group stride 1064 mod 32 banks = 8 -> conflict-free A reads.
// Crossbar/SM per k: 8 warps * (8 A-wf + 8 B-wf) = 128 cyc == fma budget.
// ---------------------------------------------------------------------------
#define GBM 128
#define GBN 64
#define SA_STRIDE 133
#define GEMM_SMEM_BYTES ((128*SA_STRIDE + 128*GBN) * 4)

__global__ void __launch_bounds__(128, 2) k_gemm_p(const float* __restrict__ x) {
    extern __shared__ float sm[];
    float* sA = sm;                     // [128][133]
    float* sB = sm + 128 * SA_STRIDE;   // [128][64]
    int tid = threadIdx.x;
    int mb = blockIdx.y * GBM;
    int nb = blockIdx.x * GBN;

    // fill A (scalar stores; odd stride forbids vector STS)
    for (int i = tid; i < 128 * 32; i += 128) {
        int r = i >> 5, c4 = (i & 31) << 2;
        float4 v = *(const float4*)(x + (mb + r) * F_ + c4);
        float* d = sA + r * SA_STRIDE + c4;
        d[0] = v.x; d[1] = v.y; d[2] = v.z; d[3] = v.w;
    }
    // fill B slice (k-major rows of 64)
    for (int i = tid; i < 128 * 16; i += 128) {
        int k = i >> 4, c4 = (i & 15) << 2;
        *(float4*)(sB + k * GBN + c4) = *(const float4*)(g_Wc + k * NPRE + nb + c4);
    }
    __syncthreads();

    int cg = tid & 7, rg = tid >> 3;    // 8 col-groups, 16 row-groups
    int c0 = cg << 3, r0 = rg << 3;     // 8 cols, 8 rows per thread

    U64 acc[8][4];
#pragma unroll
    for (int i = 0; i < 8; i++)
#pragma unroll
        for (int j = 0; j < 4; j++) acc[i][j] = 0ull;

#pragma unroll 4
    for (int k = 0; k < 128; k++) {
        ulonglong2 b01 = *(const ulonglong2*)(sB + k*GBN + c0);
        ulonglong2 b23 = *(const ulonglong2*)(sB + k*GBN + c0 + 4);
#pragma unroll
        for (int i = 0; i < 8; i++) {
            U64 p = pack2(sA[(r0+i)*SA_STRIDE + k]);
            fma2(acc[i][0], p, b01.x); fma2(acc[i][1], p, b01.y);
            fma2(acc[i][2], p, b23.x); fma2(acc[i][3], p, b23.y);
        }
    }

#pragma unroll
    for (int i = 0; i < 8; i++) {
        float* dst = g_P + (long)(mb + r0 + i) * NPRE + nb + c0;
        ulonglong2 v0; v0.x = acc[i][0]; v0.y = acc[i][1];
        *(ulonglong2*)dst = v0;
        ulonglong2 v1; v1.x = acc[i][2]; v1.y = acc[i][3];
        *(ulonglong2*)(dst + 4) = v1;
    }
}

// ---------------------------------------------------------------------------
// Recurrent kernel v4 (REVERTED to round-4/5 measured-best: 1155 us)
// ---------------------------------------------------------------------------
#define OFF_W2  0
#define OFF_B0  12288
#define OFF_B1  12480
#define OFF_HP  12672
#define OFF_MH  12800
#define OFF_G   13184
#define OFF_H   13952
#define OFF_Z2  14080
#define RNN_SMEM_FLOATS 14336
#define RNN_SMEM_BYTES  (RNN_SMEM_FLOATS * 4)

__global__ void __launch_bounds__(256, 1) k_rnn(const float* __restrict__ gbias,
                                                const float* __restrict__ gruk,
                                                float* __restrict__ out) {
    extern __shared__ float sm[];
    float* sW2 = sm + OFF_W2;
    float* sB0 = sm + OFF_B0;
    float* sB1 = sm + OFF_B1;
    float* sHP = sm + OFF_HP;
    float* sMH = sm + OFF_MH;
    float* sG  = sm + OFF_G;
    float* sH  = sm + OFF_H;
    U64*   sZ2 = (U64*)(sm + OFF_Z2);

    int tid = threadIdx.x;
    int b0  = blockIdx.x * 2;

    for (int i = tid; i < (64*192)/4; i += 256)
        *(float4*)(sW2 + i*4) = *(const float4*)(gruk + 128*192 + i*4);
    if (tid < 96)
        *(float4*)(sB0 + tid*4) = *(const float4*)(gbias + tid*4);
    if (tid < 128) sH[tid] = 0.f;

    U64 w1a[32], w1b[32];
#pragma unroll
    for (int i = 0; i < 32; i++) {
        ulonglong2 v = *(const ulonglong2*)(g_W1p + i * 1024 + (tid << 2));
        w1a[i] = v.x; w1b[i] = v.y;
    }

    int re = tid >> 6, ue = tid & 63;
    int hf = (tid < 96) ? 0 : 1;
    int j2 = (tid < 96) ? tid : (tid - 96);
    int kb = hf << 5;

    const int SEQ = B_ * T_ * UU;
    const float* PZ0 = g_P + (long)(b0)     * T_ * NPRE + tid;
    const float* PZ1 = g_P + (long)(b0 + 1) * T_ * NPRE + tid;
    const float* PG  = g_P + (long)(b0 + re)* T_ * NPRE + 128 + ue;

    float cz0=0,cz1=0,cz2=0,cz3=0, cg0=0,cg1=0,cg2=0;
    if (tid < 64) {
        cz0 = PZ0[0];  cz1 = PZ0[64];
        cz2 = PZ1[0];  cz3 = PZ1[64];
    }
    if (tid < 128) {
        cg0 = PG[0];   cg1 = PG[64];  cg2 = PG[128];
    }
    __syncthreads();

#pragma unroll 1
    for (int t = 0; t < T_; t++) {
        int tn = (t + 1 < T_) ? (t + 1) : t;
        long offn = (long)tn * NPRE;
        float nz0=0,nz1=0,nz2=0,nz3=0, ng0=0,ng1=0,ng2=0;
        if (tid < 64) {
            nz0 = PZ0[offn];      nz1 = PZ0[offn + 64];
            nz2 = PZ1[offn];      nz3 = PZ1[offn + 64];
        }
        if (tid < 128) {
            ng0 = PG[offn];  ng1 = PG[offn + 64];  ng2 = PG[offn + 128];
        }

        const ulonglong2* h0 = (const ulonglong2*)(sH);
        const ulonglong2* h1 = (const ulonglong2*)(sH + 64);
        U64 a00 = 0ull, a01 = 0ull, a10 = 0ull, a11 = 0ull;
#pragma unroll
        for (int i = 0; i < 16; i++) {
            ulonglong2 ha = h0[i];
            ulonglong2 hb = h1[i];
            fma2(a00, ha.x, w1a[2*i]);   fma2(a01, ha.x, w1b[2*i]);
            fma2(a10, hb.x, w1a[2*i]);   fma2(a11, hb.x, w1b[2*i]);
            fma2(a00, ha.y, w1a[2*i+1]); fma2(a01, ha.y, w1b[2*i+1]);
            fma2(a10, hb.y, w1a[2*i+1]); fma2(a11, hb.y, w1b[2*i+1]);
        }
        float y00 = hsum2(a00), y01 = hsum2(a01);
        float y10 = hsum2(a10), y11 = hsum2(a11);

        if (tid < 64) {
            float qmu0 = y00 + cz0, qlv0 = y01 + cz1;
            float qmu1 = y10 + cz2, qlv1 = y11 + cz3;
            float z0 = 0.5f * __expf(qlv0) + qmu0;
            float z1 = 0.5f * __expf(qlv1) + qmu1;
            sZ2[tid]      = pack2(z0);
            sZ2[64 + tid] = pack2(z1);
            int base0 = (b0 * T_ + t) * UU + tid;
            int base1 = base0 + T_ * UU;
            out[base0]          = z0;
            out[base0 + SEQ]    = qmu0;
            out[base0 + 3*SEQ]  = qlv0;
            out[base1]          = z1;
            out[base1 + SEQ]    = qmu1;
            out[base1 + 3*SEQ]  = qlv1;
        } else if (tid < 128) {
            int u = tid - 64;
            int base0 = (b0 * T_ + t) * UU + u;
            int base1 = base0 + T_ * UU;
            out[base0 + 2*SEQ] = y00;
            out[base0 + 4*SEQ] = y01;
            out[base1 + 2*SEQ] = y10;
            out[base1 + 4*SEQ] = y11;
        } else if (tid < 160) {
            int j = tid - 128;
            *(float2*)(sHP + 2*j)       = make_float2(y00, y01);
            *(float2*)(sHP + 64 + 2*j)  = make_float2(y10, y11);
        } else {
            int j = tid - 160;
            *(float2*)(sMH + 2*j)        = make_float2(y00, y01);
            *(float2*)(sMH + 192 + 2*j)  = make_float2(y10, y11);
        }
        __syncthreads();

        if (tid < 192) {
            U64 g0 = 0ull, g1 = 0ull;
            const float* w2 = sW2 + (j2 << 1);
#pragma unroll
            for (int kk = 0; kk < 32; kk += 2) {
                int k = kb + kk;
                ulonglong2 z0 = *(const ulonglong2*)(sZ2 + k);
                ulonglong2 z1 = *(const ulonglong2*)(sZ2 + 64 + k);
                U64 wa = *(const U64*)(w2 + k * 192);
                U64 wb = *(const U64*)(w2 + (k+1) * 192);
                fma2(g0, z0.x, wa); fma2(g1, z1.x, wa);
                fma2(g0, z0.y, wb); fma2(g1, z1.y, wb);
            }
            *(U64*)(sG + ((hf << 1) + 0) * 192 + (j2 << 1)) = g0;
            *(U64*)(sG + ((hf << 1) + 1) * 192 + (j2 << 1)) = g1;
        }
        __syncthreads();

        if (tid < 128) {
            const float* Ga = sG + re * 192;
            const float* Gb = sG + (2 + re) * 192;
            float hp  = sHP[re * 64 + ue];
            float mhz = sMH[re * 192 + ue]        + sB1[ue];
            float mhr = sMH[re * 192 + 64 + ue]   + sB1[64 + ue];
            float mhh = sMH[re * 192 + 128 + ue]  + sB1[128 + ue];
            float mxz = cg0 + Ga[ue]        + Gb[ue]        + sB0[ue];
            float mxr = cg1 + Ga[64 + ue]   + Gb[64 + ue]   + sB0[64 + ue];
            float mxh = cg2 + Ga[128 + ue]  + Gb[128 + ue]  + sB0[128 + ue];
            float zt = sigmoid_f(mxz + mhz);
            float rt = sigmoid_f(mxr + mhr);
            float hh = tanh_exp(mxh + rt * mhh);
            sH[re * 64 + ue] = zt * hp + (1.f - zt) * hh;
        }
        __syncthreads();

        cz0 = nz0; cz1 = nz1; cz2 = nz2; cz3 = nz3;
        cg0 = ng0; cg1 = ng1; cg2 = ng2;
    }
}

// ---------------------------------------------------------------------------
extern "C" void kernel_launch(void* const* d_in, const int* in_sizes, int n_in,
                              void* d_out, int out_size) {
    const float* x   = (const float*)d_in[0];
    const float* Win = (const float*)d_in[1];
    const float* S   = (const float*)d_in[2];
    const float* Emu = (const float*)d_in[3];
    const float* Elv = (const float*)d_in[4];
    const float* Pmu = (const float*)d_in[5];
    const float* Plv = (const float*)d_in[6];
    const float* Wg  = (const float*)d_in[7];
    const float* R   = (const float*)d_in[8];
    const float* gb  = (const float*)d_in[9];

    cudaFuncSetAttribute(k_gemm_p, cudaFuncAttributeMaxDynamicSharedMemorySize, GEMM_SMEM_BYTES);
    cudaFuncSetAttribute(k_rnn,    cudaFuncAttributeMaxDynamicSharedMemorySize, RNN_SMEM_BYTES);

    k_prep_wc<<<128, 320>>>(Win, Emu, Elv, Wg);
    k_prep_w1<<<64, 512>>>(S, Pmu, Plv, Emu, Elv, R);

    dim3 gg(5, 2048);   // N-tiles fastest: same-A blocks adjacent -> L2 reuse
    k_gemm_p<<<gg, 128, GEMM_SMEM_BYTES>>>(x);

    k_rnn<<<128, 256, RNN_SMEM_BYTES>>>(gb, Wg, (float*)d_out);
}